// round 13
// baseline (speedup 1.0000x reference)
#include <cuda_runtime.h>
#include <math.h>

#define BB 64

// ---------------------------------------------------------------------------
// Scratch
// ---------------------------------------------------------------------------
__device__ float g_pooled1[BB * 3];
__device__ float g_w1t[BB * 64 * 168];           // tf32-rounded, padded [co][ci][kh][8]
__device__ float g_conv1[BB * 64 * 112 * 112];
__device__ float g_pool1[BB * 64 * 56 * 56];     // tf32-rounded (conv2 input)
__device__ float g_pooled2[BB * 64];
__device__ float g_w2[BB * 128 * 64 * 9];        // tf32-rounded
__device__ float g_conv2[BB * 128 * 28 * 28];
__device__ float g_pool2[BB * 128 * 14 * 14];
__device__ float g_rc1[BB * 256 * 49];
__device__ float g_rc2[BB * 256 * 49];
__device__ float g_rs[BB * 256 * 49];

__device__ float g_sum1[64],  g_sq1[64];
__device__ float g_sum2[128], g_sq2[128];
__device__ float g_scr1[256], g_shr1[256];
__device__ float g_scr2[256], g_shr2[256];
__device__ float g_scs[256],  g_shs[256];

__device__ float g_M[50 * 256];
__device__ float g_b2[50];

// ---------------------------------------------------------------------------
// per-channel stats of rc1 + finalize scale/shift
// ---------------------------------------------------------------------------
__global__ void k_chstats(const float* __restrict__ g, const float* __restrict__ be) {
    int c = blockIdx.x;
    float s = 0.f, q = 0.f;
    for (int t = threadIdx.x; t < BB * 49; t += 128) {
        int b = t / 49, p = t - b * 49;
        float v = g_rc1[(b * 256 + c) * 49 + p];
        s += v; q += v * v;
    }
    for (int o = 16; o; o >>= 1) {
        s += __shfl_down_sync(0xffffffffu, s, o);
        q += __shfl_down_sync(0xffffffffu, q, o);
    }
    __shared__ float rs[4], rq[4];
    int w = threadIdx.x >> 5;
    if ((threadIdx.x & 31) == 0) { rs[w] = s; rq[w] = q; }
    __syncthreads();
    if (threadIdx.x == 0) {
        float su = rs[0] + rs[1] + rs[2] + rs[3];
        float sq = rq[0] + rq[1] + rq[2] + rq[3];
        float m = su * (1.f / 3136.f);
        float v = sq * (1.f / 3136.f) - m * m;
        float sc = g[c] * rsqrtf(v + 1e-5f);
        g_scr1[c] = sc;
        g_shr1[c] = be[c] - m * sc;
    }
}

// stats of rc2 AND rs + finalize both scale/shifts
__global__ void k_chstats2(const float* __restrict__ g2, const float* __restrict__ be2,
                           const float* __restrict__ gs, const float* __restrict__ bes) {
    int c = blockIdx.x;
    float s2 = 0.f, q2 = 0.f, ss = 0.f, qs = 0.f;
    for (int t = threadIdx.x; t < BB * 49; t += 128) {
        int b = t / 49, p = t - b * 49;
        float v = g_rc2[(b * 256 + c) * 49 + p];
        s2 += v; q2 += v * v;
        float u = g_rs[(b * 256 + c) * 49 + p];
        ss += u; qs += u * u;
    }
    for (int o = 16; o; o >>= 1) {
        s2 += __shfl_down_sync(0xffffffffu, s2, o);
        q2 += __shfl_down_sync(0xffffffffu, q2, o);
        ss += __shfl_down_sync(0xffffffffu, ss, o);
        qs += __shfl_down_sync(0xffffffffu, qs, o);
    }
    __shared__ float r[4][4];
    int w = threadIdx.x >> 5;
    if ((threadIdx.x & 31) == 0) { r[w][0] = s2; r[w][1] = q2; r[w][2] = ss; r[w][3] = qs; }
    __syncthreads();
    if (threadIdx.x == 0) {
        float su2 = r[0][0] + r[1][0] + r[2][0] + r[3][0];
        float sq2 = r[0][1] + r[1][1] + r[2][1] + r[3][1];
        float sus = r[0][2] + r[1][2] + r[2][2] + r[3][2];
        float sqs = r[0][3] + r[1][3] + r[2][3] + r[3][3];
        float m2 = su2 * (1.f / 3136.f);
        float v2 = sq2 * (1.f / 3136.f) - m2 * m2;
        float c2 = g2[c] * rsqrtf(v2 + 1e-5f);
        g_scr2[c] = c2;
        g_shr2[c] = be2[c] - m2 * c2;
        float ms = sus * (1.f / 3136.f);
        float vs = sqs * (1.f / 3136.f) - ms * ms;
        float cs = gs[c] * rsqrtf(vs + 1e-5f);
        g_scs[c] = cs;
        g_shs[c] = bes[c] - ms * cs;
    }
}

// ---------------------------------------------------------------------------
// Stage-1 global pool (block 0 zeroes accumulators)
// ---------------------------------------------------------------------------
__global__ void k_pooled1(const float* __restrict__ imgs) {
    int bc = blockIdx.x;
    int tid = threadIdx.x;
    if (bc == 0) {
        for (int i = tid; i < BB * 64; i += 256) g_pooled2[i] = 0.f;
        if (tid < 64)  { g_sum1[tid] = 0.f; g_sq1[tid] = 0.f; }
        if (tid < 128) { g_sum2[tid] = 0.f; g_sq2[tid] = 0.f; }
    }
    const float* p = imgs + (long)bc * 50176;
    float s = 0.f;
    for (int i = tid; i < 50176; i += 256) s += p[i];
    __shared__ float red[256];
    red[tid] = s; __syncthreads();
    for (int o = 128; o; o >>= 1) { if (tid < o) red[tid] += red[tid + o]; __syncthreads(); }
    if (tid == 0) g_pooled1[bc] = red[0] * (1.f / 50176.f);
}

// ---------------------------------------------------------------------------
// w1agg with fused attn1 (one b per block: 10752 % 256 == 0)
// aggregate + tf32-round + pad into [b][co][ci][kh][8] (kw slot 7 = 0)
// ---------------------------------------------------------------------------
__global__ void k_w1agg(const float* __restrict__ dy1, const float* __restrict__ fc1,
                        const float* __restrict__ fc2, const float* __restrict__ fc2b) {
    __shared__ float sh_h[8], sh_lg[8], sh_attn[8];
    int blk = blockIdx.x;
    int b = blk / 42;
    int tid = threadIdx.x;
    if (tid < 8) {
        float s = 0.f;
        for (int c = 0; c < 3; c++) s += g_pooled1[b * 3 + c] * fc1[tid * 3 + c];
        sh_h[tid] = fmaxf(s, 0.f);
    }
    __syncthreads();
    if (tid < 8) {
        float s = fc2b[tid];
        for (int j = 0; j < 8; j++) s += sh_h[j] * fc2[tid * 8 + j];
        sh_lg[tid] = s;
    }
    __syncthreads();
    if (tid == 0) {
        float mx = -1e30f;
        for (int k = 0; k < 8; k++) mx = fmaxf(mx, sh_lg[k]);
        float e[8], den = 0.f;
        for (int k = 0; k < 8; k++) { e[k] = expf(sh_lg[k] - mx); den += e[k]; }
        float inv = 1.f / den;
        for (int k = 0; k < 8; k++) sh_attn[k] = e[k] * inv;
    }
    __syncthreads();

    int idx = blk * 256 + tid;
    int r = idx - b * 10752;
    int co = r / 168, r2 = r - co * 168;
    int ci = r2 / 56, r3 = r2 - ci * 56;
    int kh = r3 >> 3, kw = r3 & 7;
    float s = 0.f;
    if (kw < 7) {
        int i = co * 147 + ci * 49 + kh * 7 + kw;
#pragma unroll
        for (int k = 0; k < 8; k++) s += sh_attn[k] * dy1[k * 9408 + i];
    }
    unsigned tv; asm("cvt.rna.tf32.f32 %0, %1;" : "=r"(tv) : "f"(s));
    g_w1t[idx] = __uint_as_float(tv);
}

// ---------------------------------------------------------------------------
// Tail fold in ONE kernel: block i computes T-row (smem), M-row, and b2[i].
// T = fcw@wo (row i), M[i,:] = Trow@wv, b2[i] = fcw[i,:]@bo + fcb[i].
// ---------------------------------------------------------------------------
__global__ void __launch_bounds__(256) k_foldfused(
        const float* __restrict__ fcw, const float* __restrict__ wo,
        const float* __restrict__ wv, const float* __restrict__ bo,
        const float* __restrict__ fcb) {
    __shared__ float s_row[256];
    __shared__ float s_T[1024];
    int i = blockIdx.x, tid = threadIdx.x;
    s_row[tid] = fcw[i * 256 + tid];
    __syncthreads();
    for (int j = tid; j < 1024; j += 256) {
        float s = 0.f;
        for (int c = 0; c < 256; c++) s += s_row[c] * wo[c * 1024 + j];
        s_T[j] = s;
    }
    __syncthreads();
    {
        float s = 0.f;
        for (int j = 0; j < 1024; j++) s += s_T[j] * wv[j * 256 + tid];
        g_M[i * 256 + tid] = s;
    }
    if (tid < 32) {
        float s = 0.f;
        for (int c = tid; c < 256; c += 32) s += s_row[c] * bo[c];
        for (int o = 16; o; o >>= 1) s += __shfl_down_sync(0xffffffffu, s, o);
        if (tid == 0) g_b2[i] = s + fcb[i];
    }
}

// ---------------------------------------------------------------------------
// Conv1 via tf32 mma.sync implicit GEMM. 32 co per block (R12 proven form).
// grid (49, 2 cog, 64 b), 256 threads.
// ---------------------------------------------------------------------------
#define W_STRIDE 172
extern __shared__ float smemBuf[];
__global__ void __launch_bounds__(256, 3) k_conv1(const float* __restrict__ imgs) {
    float* s_in = smemBuf;                   // [ci][37][64]
    float* s_w = smemBuf + 7104;             // [32 co][W_STRIDE]
    float* s_stat = smemBuf + 7104 + 32 * W_STRIDE;   // 64
    int b = blockIdx.z, cog = blockIdx.y;
    int tr = blockIdx.x / 7, tc = blockIdx.x - tr * 7;
    int oh0 = tr * 16, ow0 = tc * 16;
    int tid = threadIdx.x;

    if (tid < 64) s_stat[tid] = 0.f;

    const float* wt = g_w1t + b * 10752 + cog * 5376;
    for (int t = tid; t < 5376; t += 256)
        s_w[t + (t / 168) * 4] = wt[t];

    int ih0 = 2 * oh0 - 3, iw0 = 2 * ow0 - 3;
#pragma unroll 1
    for (int ci = 0; ci < 3; ci++) {
        const float* ip = imgs + (long)(b * 3 + ci) * 50176;
        for (int u = tid; u < 2368; u += 256) {
            int r = u >> 6, c = u & 63;
            if (c < 38) {
                int ih = ih0 + r, iw = iw0 + c;
                float v = 0.f;
                if ((unsigned)ih < 224u && (unsigned)iw < 224u)
                    v = ip[ih * 224 + iw];
                unsigned tv; asm("cvt.rna.tf32.f32 %0, %1;" : "=r"(tv) : "f"(v));
                s_in[ci * 2368 + u] = __uint_as_float(tv);
            }
        }
    }
    __syncthreads();

    int w = tid >> 5, lane = tid & 31;
    int gid = lane >> 2, tig = lane & 3;

    float acc[2][4][4];
#pragma unroll
    for (int mt = 0; mt < 2; mt++)
#pragma unroll
        for (int nt = 0; nt < 4; nt++)
#pragma unroll
            for (int k = 0; k < 4; k++) acc[mt][nt][k] = 0.f;

    int bq[4];
#pragma unroll
    for (int nt = 0; nt < 4; nt++) bq[nt] = (nt * 8 + gid) * W_STRIDE + tig;
    int abase0 = (2 * (2 * w + 0)) * 64 + 2 * gid + tig;
    int abase1 = (2 * (2 * w + 1)) * 64 + 2 * gid + tig;

#pragma unroll 1
    for (int ci = 0; ci < 3; ci++) {
#pragma unroll
        for (int kh = 0; kh < 7; kh++) {
            int wbase = ci * 56 + kh * 8;
            int aoff = ci * 2368 + kh * 64;
            unsigned bf0[4], bf1[4];
#pragma unroll
            for (int nt = 0; nt < 4; nt++) {
                bf0[nt] = __float_as_uint(s_w[bq[nt] + wbase]);
                bf1[nt] = __float_as_uint(s_w[bq[nt] + wbase + 4]);
            }
#pragma unroll
            for (int mt = 0; mt < 2; mt++) {
                int a = aoff + (mt ? abase1 : abase0);
                unsigned a0 = __float_as_uint(s_in[a]);
                unsigned a1 = __float_as_uint(s_in[a + 16]);
                unsigned a2 = __float_as_uint(s_in[a + 4]);
                unsigned a3 = __float_as_uint(s_in[a + 20]);
#pragma unroll
                for (int nt = 0; nt < 4; nt++) {
                    asm volatile(
                        "mma.sync.aligned.m16n8k8.row.col.f32.tf32.tf32.f32 "
                        "{%0,%1,%2,%3}, {%4,%5,%6,%7}, {%8,%9}, {%0,%1,%2,%3};"
                        : "+f"(acc[mt][nt][0]), "+f"(acc[mt][nt][1]),
                          "+f"(acc[mt][nt][2]), "+f"(acc[mt][nt][3])
                        : "r"(a0), "r"(a1), "r"(a2), "r"(a3),
                          "r"(bf0[nt]), "r"(bf1[nt]));
                }
            }
        }
    }

#pragma unroll
    for (int mt = 0; mt < 2; mt++) {
        int oh = oh0 + 2 * w + mt;
#pragma unroll
        for (int nt = 0; nt < 4; nt++) {
            int co = cog * 32 + nt * 8 + 2 * tig;
            long base0 = ((long)(b * 64 + co)) * 12544 + oh * 112 + ow0;
            g_conv1[base0 + gid] = acc[mt][nt][0];
            g_conv1[base0 + 12544 + gid] = acc[mt][nt][1];
            g_conv1[base0 + gid + 8] = acc[mt][nt][2];
            g_conv1[base0 + 12544 + gid + 8] = acc[mt][nt][3];
        }
    }

#pragma unroll
    for (int nt = 0; nt < 4; nt++) {
        float s0 = 0.f, q0 = 0.f, s1 = 0.f, q1 = 0.f;
#pragma unroll
        for (int mt = 0; mt < 2; mt++) {
            float v;
            v = acc[mt][nt][0]; s0 += v; q0 += v * v;
            v = acc[mt][nt][2]; s0 += v; q0 += v * v;
            v = acc[mt][nt][1]; s1 += v; q1 += v * v;
            v = acc[mt][nt][3]; s1 += v; q1 += v * v;
        }
#pragma unroll
        for (int o = 16; o >= 4; o >>= 1) {
            s0 += __shfl_xor_sync(0xffffffffu, s0, o);
            q0 += __shfl_xor_sync(0xffffffffu, q0, o);
            s1 += __shfl_xor_sync(0xffffffffu, s1, o);
            q1 += __shfl_xor_sync(0xffffffffu, q1, o);
        }
        if (gid == 0) {
            int lco = nt * 8 + 2 * tig;
            atomicAdd(&s_stat[lco], s0);
            atomicAdd(&s_stat[32 + lco], q0);
            atomicAdd(&s_stat[lco + 1], s1);
            atomicAdd(&s_stat[32 + lco + 1], q1);
        }
    }
    __syncthreads();
    if (tid < 32) {
        atomicAdd(&g_sum1[cog * 32 + tid], s_stat[tid]);
        atomicAdd(&g_sq1[cog * 32 + tid], s_stat[32 + tid]);
    }
}
#define CONV1_SMEM ((7104 + 32 * W_STRIDE + 64) * 4)

// ---------------------------------------------------------------------------
// BN1 + maxpool3 s2 p1 (scale/shift computed inline from sums); tf32 output
// ---------------------------------------------------------------------------
extern __shared__ float s_plane[];
__global__ void __launch_bounds__(256) k_bnpool1(const float* __restrict__ g,
                                                 const float* __restrict__ be) {
    int c = blockIdx.x, b = blockIdx.y;
    int tid = threadIdx.x;
    const float* ip = g_conv1 + (long)(b * 64 + c) * 12544;
#pragma unroll
    for (int k = 0; k < 49; k++) s_plane[tid + 256 * k] = ip[tid + 256 * k];
    __syncthreads();

    float m_ = g_sum1[c] / 802816.f;
    float v_ = g_sq1[c] / 802816.f - m_ * m_;
    float sc = g[c] * rsqrtf(v_ + 1e-5f);
    float sh = be[c] - m_ * sc;

    float* op = g_pool1 + (b * 64 + c) * 3136;
    float s = 0.f;
#pragma unroll
    for (int k = 0; k < 13; k++) {
        int p = tid + 256 * k;
        if (p < 3136) {
            int oh = p / 56, ow = p - oh * 56;
            float m = -1e30f;
#pragma unroll
            for (int r = 0; r < 3; r++) {
                int ih = 2 * oh - 1 + r;
                if ((unsigned)ih >= 112u) continue;
#pragma unroll
                for (int cc = 0; cc < 3; cc++) {
                    int iw = 2 * ow - 1 + cc;
                    if ((unsigned)iw >= 112u) continue;
                    m = fmaxf(m, s_plane[ih * 112 + iw] * sc + sh);
                }
            }
            unsigned tv; asm("cvt.rna.tf32.f32 %0, %1;" : "=r"(tv) : "f"(m));
            op[p] = __uint_as_float(tv);
            s += m;
        }
    }
    for (int o = 16; o; o >>= 1) s += __shfl_down_sync(0xffffffffu, s, o);
    __shared__ float s_red;
    if (tid == 0) s_red = 0.f;
    __syncthreads();
    if ((tid & 31) == 0) atomicAdd(&s_red, s);
    __syncthreads();
    if (tid == 0) atomicAdd(&g_pooled2[b * 64 + c], s_red);
}
#define POOL1_SMEM (12544 * 4)

// ---------------------------------------------------------------------------
// w2agg with fused attn2 (one b per block: 73728 % 256 == 0); tf32-rounded
// ---------------------------------------------------------------------------
__global__ void k_w2agg(const float* __restrict__ dy2, const float* __restrict__ fc1,
                        const float* __restrict__ fc2, const float* __restrict__ fc2b) {
    __shared__ float sh_h[17], sh_lg[8], sh_attn[8];
    int blk = blockIdx.x;
    int b = blk / 288;
    int tid = threadIdx.x;
    if (tid < 17) {
        float s = 0.f;
        for (int c = 0; c < 64; c++)
            s += (g_pooled2[b * 64 + c] * (1.f / 3136.f)) * fc1[tid * 64 + c];
        sh_h[tid] = fmaxf(s, 0.f);
    }
    __syncthreads();
    if (tid < 8) {
        float s = fc2b[tid];
        for (int j = 0; j < 17; j++) s += sh_h[j] * fc2[tid * 17 + j];
        sh_lg[tid] = s;
    }
    __syncthreads();
    if (tid == 0) {
        float mx = -1e30f;
        for (int k = 0; k < 8; k++) mx = fmaxf(mx, sh_lg[k]);
        float e[8], den = 0.f;
        for (int k = 0; k < 8; k++) { e[k] = expf(sh_lg[k] - mx); den += e[k]; }
        float inv = 1.f / den;
        for (int k = 0; k < 8; k++) sh_attn[k] = e[k] * inv;
    }
    __syncthreads();

    int idx = blk * 256 + tid;
    int i = idx - b * 73728;
    float s = 0.f;
#pragma unroll
    for (int k = 0; k < 8; k++) s += sh_attn[k] * dy2[k * 73728 + i];
    unsigned tv; asm("cvt.rna.tf32.f32 %0, %1;" : "=r"(tv) : "f"(s));
    g_w2[idx] = __uint_as_float(tv);
}

// ---------------------------------------------------------------------------
// Conv2 via tf32 mma.sync (R11 proven form: 128 co/block).
// grid (7 rowblk, 64 b), 256 threads, warps 0-6 mma.
// ---------------------------------------------------------------------------
__global__ void __launch_bounds__(256, 2) k_conv2() {
    float* s_in = smemBuf;                 // 4698
    float* s_w = smemBuf + 4698;           // 10368
    float* s_stat = smemBuf + 4698 + 10368;
    int rowblk = blockIdx.x, b = blockIdx.y;
    int tid = threadIdx.x;

    for (int t = tid; t < 4698; t += 256) s_in[t] = 0.f;
    s_stat[tid] = 0.f;

    int ih0 = 8 * rowblk - 1;
    int ldp[8], stp[8];
#pragma unroll
    for (int k = 0; k < 8; k++) {
        int e2 = tid + 256 * k;
        if (e2 < 2016) {
            int ci = e2 / 252, rem = e2 - ci * 252;
            int ir = rem / 28, iw2 = rem - ir * 28;
            int ih = ih0 + ir;
            ldp[k] = (ih >= 0) ? (ci * 3136 + ih * 56 + 2 * iw2) : -1;
            stp[k] = ir * 522 + (2 * iw2 + 1) * 9 + ci;
        } else { ldp[k] = -1; stp[k] = 0; }
    }

    int w = tid >> 5, lane = tid & 31;
    int gid = lane >> 2, tig = lane & 3;
    int q0 = 16 * w + gid, q1 = q0 + 8;
    int ohl0 = q0 / 28, owl0 = q0 - 28 * ohl0;
    int ohl1 = q1 / 28, owl1 = q1 - 28 * ohl1;
    int pb0 = 2 * ohl0 * 522 + 2 * owl0 * 9 + tig;
    int pb1 = 2 * ohl1 * 522 + 2 * owl1 * 9 + tig;

    float acc[16][4];
#pragma unroll
    for (int nt = 0; nt < 16; nt++)
#pragma unroll
        for (int k = 0; k < 4; k++) acc[nt][k] = 0.f;

    const float* ib = g_pool1 + (long)(b * 64) * 3136;
    const float* wb = g_w2 + b * 73728;
    int half = tid & 1, co_t = tid >> 1;

#pragma unroll 1
    for (int c0 = 0; c0 < 64; c0 += 8) {
        __syncthreads();
#pragma unroll
        for (int k = 0; k < 8; k++) {
            if (ldp[k] >= 0) {
                float2 v = *(const float2*)(ib + c0 * 3136 + ldp[k]);
                s_in[stp[k]] = v.x;
                s_in[stp[k] + 9] = v.y;
            }
        }
        {
            const float4* src = (const float4*)(wb + co_t * 576 + c0 * 9 + half * 36);
            int sb = co_t * 9;
            int cb = half * 4;
#pragma unroll
            for (int q = 0; q < 9; q++) {
                float4 f = src[q];
                int e0 = 4 * q;
                s_w[((e0    ) % 9) * 1152 + sb + cb + (e0    ) / 9] = f.x;
                s_w[((e0 + 1) % 9) * 1152 + sb + cb + (e0 + 1) / 9] = f.y;
                s_w[((e0 + 2) % 9) * 1152 + sb + cb + (e0 + 2) / 9] = f.z;
                s_w[((e0 + 3) % 9) * 1152 + sb + cb + (e0 + 3) / 9] = f.w;
            }
        }
        __syncthreads();
        if (w < 7) {
#pragma unroll
            for (int tap = 0; tap < 9; tap++) {
                int kh = tap / 3, kw = tap - 3 * (tap / 3);
                int toff = kh * 522 + kw * 9;
                unsigned a0 = __float_as_uint(s_in[pb0 + toff]);
                unsigned a1 = __float_as_uint(s_in[pb1 + toff]);
                unsigned a2 = __float_as_uint(s_in[pb0 + toff + 4]);
                unsigned a3 = __float_as_uint(s_in[pb1 + toff + 4]);
#pragma unroll
                for (int nt = 0; nt < 16; nt++) {
                    int wq = tap * 1152 + (nt * 8 + gid) * 9 + tig;
                    unsigned b0 = __float_as_uint(s_w[wq]);
                    unsigned b1 = __float_as_uint(s_w[wq + 4]);
                    asm volatile(
                        "mma.sync.aligned.m16n8k8.row.col.f32.tf32.tf32.f32 "
                        "{%0,%1,%2,%3}, {%4,%5,%6,%7}, {%8,%9}, {%0,%1,%2,%3};"
                        : "+f"(acc[nt][0]), "+f"(acc[nt][1]),
                          "+f"(acc[nt][2]), "+f"(acc[nt][3])
                        : "r"(a0), "r"(a1), "r"(a2), "r"(a3),
                          "r"(b0), "r"(b1));
                }
            }
        }
    }

    if (w < 7) {
#pragma unroll
        for (int nt = 0; nt < 16; nt++) {
            int co = nt * 8 + 2 * tig;
            long o0 = ((long)(b * 128 + co)) * 784 + rowblk * 112;
            g_conv2[o0 + q0] = acc[nt][0];
            g_conv2[o0 + 784 + q0] = acc[nt][1];
            g_conv2[o0 + q1] = acc[nt][2];
            g_conv2[o0 + 784 + q1] = acc[nt][3];
            float s0 = acc[nt][0] + acc[nt][2];
            float sq0 = acc[nt][0] * acc[nt][0] + acc[nt][2] * acc[nt][2];
            float s1 = acc[nt][1] + acc[nt][3];
            float sq1 = acc[nt][1] * acc[nt][1] + acc[nt][3] * acc[nt][3];
#pragma unroll
            for (int o = 16; o >= 4; o >>= 1) {
                s0 += __shfl_xor_sync(0xffffffffu, s0, o);
                sq0 += __shfl_xor_sync(0xffffffffu, sq0, o);
                s1 += __shfl_xor_sync(0xffffffffu, s1, o);
                sq1 += __shfl_xor_sync(0xffffffffu, sq1, o);
            }
            if (gid == 0) {
                atomicAdd(&s_stat[co], s0);
                atomicAdd(&s_stat[128 + co], sq0);
                atomicAdd(&s_stat[co + 1], s1);
                atomicAdd(&s_stat[128 + co + 1], sq1);
            }
        }
    }
    __syncthreads();
    if (tid < 128) {
        atomicAdd(&g_sum2[tid], s_stat[tid]);
        atomicAdd(&g_sq2[tid], s_stat[128 + tid]);
    }
}
#define CONV2_SMEM ((4698 + 10368 + 256) * 4)

// ---------------------------------------------------------------------------
// BN2 + maxpool3 s2 p1: 28->14 (scale/shift inline)
// ---------------------------------------------------------------------------
__global__ void k_bnpool2(const float* __restrict__ g, const float* __restrict__ be) {
    int b = blockIdx.y, c = blockIdx.x;
    int p = threadIdx.x;
    if (p >= 196) return;
    int oh = p / 14, ow = p - oh * 14;
    float m_ = g_sum2[c] / 50176.f;
    float v_ = g_sq2[c] / 50176.f - m_ * m_;
    float sc = g[c] * rsqrtf(v_ + 1e-5f);
    float sh = be[c] - m_ * sc;
    const float* ip = g_conv2 + (b * 128 + c) * 784;
    float m = -1e30f;
#pragma unroll
    for (int r = 0; r < 3; r++) {
        int ih = 2 * oh - 1 + r;
        if ((unsigned)ih >= 28u) continue;
#pragma unroll
        for (int cc = 0; cc < 3; cc++) {
            int iw = 2 * ow - 1 + cc;
            if ((unsigned)iw >= 28u) continue;
            m = fmaxf(m, ip[ih * 28 + iw] * sc + sh);
        }
    }
    g_pool2[(b * 128 + c) * 196 + p] = m;
}

// ---------------------------------------------------------------------------
// resconv1: 128->256 3x3 s2, 14->7. 4 batches/block, pipelined staging.
// ---------------------------------------------------------------------------
__global__ void __launch_bounds__(196) k_resconv1(const float* __restrict__ w) {
    __shared__ __align__(16) float s_in[4 * 1080];
    __shared__ __align__(16) float s_w[32 * 48];
    int bq = blockIdx.y, cog = blockIdx.x;
    int b0 = bq * 4;
    int tid = threadIdx.x;
    int px = tid % 49, yq = tid / 49;
    int oh = px / 7, ow = px - oh * 7;

    for (int t = tid; t < 4320; t += 196) s_in[t] = 0.f;
    for (int t = tid; t < 1536; t += 196) s_w[t] = 0.f;

    int ld[16], sidx[16];
#pragma unroll
    for (int k = 0; k < 16; k++) {
        int t = tid + 196 * k;
        int bl = t / 784, rem = t - bl * 784;
        int ci = rem / 196, p = rem - ci * 196;
        int r = p / 14, c = p - r * 14;
        ld[k] = bl * 25088 + rem;
        sidx[k] = bl * 1080 + ci * 270 + (r + 1) * 18 + (c + 1);
    }
    int wld[6], wst[6];
#pragma unroll
    for (int k = 0; k < 6; k++) {
        int t = tid + 196 * k;
        if (t < 1152) {
            int co = t / 36, rem = t - co * 36;
            int ci = rem / 9, k9 = rem - ci * 9;
            int kh = k9 / 3, kw = k9 - kh * 3;
            wld[k] = (cog * 32 + co) * 1152 + ci * 9 + k9;
            wst[k] = co * 48 + ci * 12 + kh * 4 + kw;
        } else { wld[k] = -1; wst[k] = 1536 - 1; }
    }
    __syncthreads();

    const float* base = g_pool2 + (long)(b0 * 128) * 196;
    float r_in[16], r_w[6];
#pragma unroll
    for (int k = 0; k < 16; k++) r_in[k] = base[ld[k]];
#pragma unroll
    for (int k = 0; k < 6; k++) r_w[k] = (wld[k] >= 0) ? w[wld[k]] : 0.f;

    float acc[4][8];
#pragma unroll
    for (int bl = 0; bl < 4; bl++)
#pragma unroll
        for (int co = 0; co < 8; co++) acc[bl][co] = 0.f;

#pragma unroll 1
    for (int c0 = 0; c0 < 128; c0 += 4) {
#pragma unroll
        for (int k = 0; k < 16; k++) s_in[sidx[k]] = r_in[k];
#pragma unroll
        for (int k = 0; k < 6; k++) if (wld[k] >= 0) s_w[wst[k]] = r_w[k];
        __syncthreads();
        if (c0 + 4 < 128) {
            const float* src = base + (c0 + 4) * 196;
#pragma unroll
            for (int k = 0; k < 16; k++) r_in[k] = src[ld[k]];
#pragma unroll
            for (int k = 0; k < 6; k++)
                if (wld[k] >= 0) r_w[k] = w[wld[k] + (c0 + 4) * 9];
        }
#pragma unroll
        for (int ci = 0; ci < 4; ci++) {
#pragma unroll
            for (int kh = 0; kh < 3; kh++) {
                float in[4][3];
#pragma unroll
                for (int bl = 0; bl < 4; bl++) {
                    int bs = bl * 1080 + ci * 270 + (2 * oh + kh) * 18 + 2 * ow;
                    in[bl][0] = s_in[bs];
                    in[bl][1] = s_in[bs + 1];
                    in[bl][2] = s_in[bs + 2];
                }
#pragma unroll
                for (int co = 0; co < 8; co++) {
                    const float4* wp = (const float4*)(s_w + (yq * 8 + co) * 48 + ci * 12 + kh * 4);
                    float4 wv = wp[0];
#pragma unroll
                    for (int bl = 0; bl < 4; bl++) {
                        acc[bl][co] += wv.x * in[bl][0];
                        acc[bl][co] += wv.y * in[bl][1];
                        acc[bl][co] += wv.z * in[bl][2];
                    }
                }
            }
        }
        __syncthreads();
    }
#pragma unroll
    for (int bl = 0; bl < 4; bl++)
#pragma unroll
        for (int co = 0; co < 8; co++)
            g_rc1[((b0 + bl) * 256 + cog * 32 + yq * 8 + co) * 49 + px] = acc[bl][co];
}

// ---------------------------------------------------------------------------
// resconv2: 256->256 3x3 s1, 7x7. bn+relu at register-load time, pipelined.
// ---------------------------------------------------------------------------
__global__ void __launch_bounds__(196) k_resconv2(const float* __restrict__ w) {
    __shared__ __align__(16) float s_in[4 * 432];
    __shared__ __align__(16) float s_w[32 * 48];
    int bq = blockIdx.y, cog = blockIdx.x;
    int b0 = bq * 4;
    int tid = threadIdx.x;
    int px = tid % 49, yq = tid / 49;
    int oh = px / 7, ow = px - oh * 7;

    for (int t = tid; t < 1728; t += 196) s_in[t] = 0.f;
    for (int t = tid; t < 1536; t += 196) s_w[t] = 0.f;

    int ld[4], sidx[4], cidx[4];
#pragma unroll
    for (int k = 0; k < 4; k++) {
        int t = tid + 196 * k;
        int bl = t / 196, rem = t - bl * 196;
        int ci = rem / 49, p = rem - ci * 49;
        int r = p / 7, c = p - r * 7;
        ld[k] = bl * 12544 + rem;
        sidx[k] = bl * 432 + ci * 108 + (r + 1) * 12 + (c + 1);
        cidx[k] = ci;
    }
    int wld[6], wst[6];
#pragma unroll
    for (int k = 0; k < 6; k++) {
        int t = tid + 196 * k;
        if (t < 1152) {
            int co = t / 36, rem = t - co * 36;
            int ci = rem / 9, k9 = rem - ci * 9;
            int kh = k9 / 3, kw = k9 - kh * 3;
            wld[k] = (cog * 32 + co) * 2304 + ci * 9 + k9;
            wst[k] = co * 48 + ci * 12 + kh * 4 + kw;
        } else { wld[k] = -1; wst[k] = 0; }
    }
    __syncthreads();

    const float* base = g_rc1 + (long)(b0 * 256) * 49;
    float r_in[4], r_w[6];
#pragma unroll
    for (int k = 0; k < 4; k++) {
        float sc = g_scr1[cidx[k]], sh = g_shr1[cidx[k]];
        r_in[k] = fmaxf(base[ld[k]] * sc + sh, 0.f);
    }
#pragma unroll
    for (int k = 0; k < 6; k++) r_w[k] = (wld[k] >= 0) ? w[wld[k]] : 0.f;

    float acc[4][8];
#pragma unroll
    for (int bl = 0; bl < 4; bl++)
#pragma unroll
        for (int co = 0; co < 8; co++) acc[bl][co] = 0.f;

#pragma unroll 1
    for (int c0 = 0; c0 < 256; c0 += 4) {
#pragma unroll
        for (int k = 0; k < 4; k++) s_in[sidx[k]] = r_in[k];
#pragma unroll
        for (int k = 0; k < 6; k++) if (wld[k] >= 0) s_w[wst[k]] = r_w[k];
        __syncthreads();
        if (c0 + 4 < 256) {
            const float* src = base + (c0 + 4) * 49;
#pragma unroll
            for (int k = 0; k < 4; k++) {
                int ch = c0 + 4 + cidx[k];
                float sc = g_scr1[ch], sh = g_shr1[ch];
                r_in[k] = fmaxf(src[ld[k]] * sc + sh, 0.f);
            }
#pragma unroll
            for (int k = 0; k < 6; k++)
                if (wld[k] >= 0) r_w[k] = w[wld[k] + (c0 + 4) * 9];
        }
#pragma unroll
        for (int ci = 0; ci < 4; ci++) {
#pragma unroll
            for (int kh = 0; kh < 3; kh++) {
                float in[4][3];
#pragma unroll
                for (int bl = 0; bl < 4; bl++) {
                    int bs = bl * 432 + ci * 108 + (oh + kh) * 12 + ow;
                    in[bl][0] = s_in[bs];
                    in[bl][1] = s_in[bs + 1];
                    in[bl][2] = s_in[bs + 2];
                }
#pragma unroll
                for (int co = 0; co < 8; co++) {
                    const float4* wp = (const float4*)(s_w + (yq * 8 + co) * 48 + ci * 12 + kh * 4);
                    float4 wv = wp[0];
#pragma unroll
                    for (int bl = 0; bl < 4; bl++) {
                        acc[bl][co] += wv.x * in[bl][0];
                        acc[bl][co] += wv.y * in[bl][1];
                        acc[bl][co] += wv.z * in[bl][2];
                    }
                }
            }
        }
        __syncthreads();
    }
#pragma unroll
    for (int bl = 0; bl < 4; bl++)
#pragma unroll
        for (int co = 0; co < 8; co++)
            g_rc2[((b0 + bl) * 256 + cog * 32 + yq * 8 + co) * 49 + px] = acc[bl][co];
}

// ---------------------------------------------------------------------------
// shortcut 1x1 s2, smem staged, scalar. grid (8 cog, 64 b), block 196.
// ---------------------------------------------------------------------------
__global__ void __launch_bounds__(196) k_shortcut(const float* __restrict__ w) {
    __shared__ __align__(16) float s_c[128 * 49];
    __shared__ __align__(16) float s_wv[32 * 128];
    int b = blockIdx.y, cog = blockIdx.x;
    int tid = threadIdx.x;
    int px = tid % 49, yq = tid / 49;

    for (int t = tid; t < 128 * 49; t += 196) {
        int ci = t / 49, p = t - ci * 49;
        int oh = p / 7, ow = p - oh * 7;
        s_c[t] = g_pool2[(b * 128 + ci) * 196 + oh * 28 + ow * 2];
    }
    for (int t = tid; t < 32 * 128; t += 196) {
        int co = t >> 7, ci = t & 127;
        s_wv[t] = w[(cog * 32 + co) * 128 + ci];
    }
    __syncthreads();

    float acc[8];
#pragma unroll
    for (int co = 0; co < 8; co++) acc[co] = 0.f;
#pragma unroll 1
    for (int cp = 0; cp < 64; cp++) {
        float in0 = s_c[(2 * cp) * 49 + px];
        float in1 = s_c[(2 * cp + 1) * 49 + px];
#pragma unroll
        for (int co = 0; co < 8; co++) {
            float2 wv = *(const float2*)(s_wv + (yq * 8 + co) * 128 + 2 * cp);
            acc[co] += wv.x * in0;
            acc[co] += wv.y * in1;
        }
    }
#pragma unroll
    for (int co = 0; co < 8; co++)
        g_rs[(b * 256 + cog * 32 + yq * 8 + co) * 49 + px] = acc[co];
}

// ---------------------------------------------------------------------------
// tail: y = mean relu(bn(rc2)+bn(rs)); out = y M^T + b2
// ---------------------------------------------------------------------------
__global__ void k_tail(float* __restrict__ out) {
    __shared__ float s_y[256];
    int b = blockIdx.x, c = threadIdx.x;
    float sc2 = g_scr2[c], sh2 = g_shr2[c], scs = g_scs[c], shs = g_shs[c];
    const float* p2 = g_rc2 + (b * 256 + c) * 49;
    const float* ps = g_rs + (b * 256 + c) * 49;
    float s = 0.f;
    for (int p = 0; p < 49; p++) {
        float v = p2[p] * sc2 + sh2 + ps[p] * scs + shs;
        s += fmaxf(v, 0.f);
    }
    s_y[c] = s * (1.f / 49.f);
    __syncthreads();
    if (c < 50) {
        float acc = g_b2[c];
        for (int k = 0; k < 256; k++) acc += s_y[k] * g_M[c * 256 + k];
        out[b * 50 + c] = acc;
    }
}

// ---------------------------------------------------------------------------
// Launch (k_conv1 is the 4th launch -> ncu profile target / control)
// ---------------------------------------------------------------------------
extern "C" void kernel_launch(void* const* d_in, const int* in_sizes, int n_in,
                              void* d_out, int out_size) {
    const float* imgs   = (const float*)d_in[0];
    const float* a1f1   = (const float*)d_in[1];
    const float* a1f2   = (const float*)d_in[2];
    const float* a1f2b  = (const float*)d_in[3];
    const float* dy1    = (const float*)d_in[4];
    const float* bn1g   = (const float*)d_in[5];
    const float* bn1b   = (const float*)d_in[6];
    const float* a2f1   = (const float*)d_in[7];
    const float* a2f2   = (const float*)d_in[8];
    const float* a2f2b  = (const float*)d_in[9];
    const float* dy2    = (const float*)d_in[10];
    const float* bn2g   = (const float*)d_in[11];
    const float* bn2b   = (const float*)d_in[12];
    const float* rc1w   = (const float*)d_in[13];
    const float* rbn1g  = (const float*)d_in[14];
    const float* rbn1b  = (const float*)d_in[15];
    const float* rc2w   = (const float*)d_in[16];
    const float* rbn2g  = (const float*)d_in[17];
    const float* rbn2b  = (const float*)d_in[18];
    const float* rsw    = (const float*)d_in[19];
    const float* rbnsg  = (const float*)d_in[20];
    const float* rbnsb  = (const float*)d_in[21];
    const float* wv     = (const float*)d_in[24];
    const float* wo     = (const float*)d_in[25];
    const float* bo     = (const float*)d_in[26];
    const float* fcw    = (const float*)d_in[27];
    const float* fcb    = (const float*)d_in[28];
    float* out = (float*)d_out;
    (void)in_sizes; (void)n_in; (void)out_size;

    static int smem_set = 0;
    if (!smem_set) {
        cudaFuncSetAttribute(k_conv1, cudaFuncAttributeMaxDynamicSharedMemorySize,
                             CONV1_SMEM);
        cudaFuncSetAttribute(k_conv1, cudaFuncAttributePreferredSharedMemoryCarveout,
                             100);
        cudaFuncSetAttribute(k_conv2, cudaFuncAttributeMaxDynamicSharedMemorySize,
                             CONV2_SMEM);
        cudaFuncSetAttribute(k_conv2, cudaFuncAttributePreferredSharedMemoryCarveout,
                             100);
        cudaFuncSetAttribute(k_bnpool1, cudaFuncAttributeMaxDynamicSharedMemorySize,
                             POOL1_SMEM);
        smem_set = 1;
    }

    // stage 1 front (block 0 of pooled1 zeroes accumulators)
    k_pooled1<<<192, 256>>>(imgs);
    k_w1agg<<<BB * 42, 256>>>(dy1, a1f1, a1f2, a1f2b);
    k_foldfused<<<50, 256>>>(fcw, wo, wv, bo, fcb);
    k_conv1<<<dim3(49, 2, BB), 256, CONV1_SMEM>>>(imgs);  // 4th (profiled)

    k_bnpool1<<<dim3(64, BB), 256, POOL1_SMEM>>>(bn1g, bn1b);

    // stage 2
    k_w2agg<<<BB * 288, 256>>>(dy2, a2f1, a2f2, a2f2b);
    k_conv2<<<dim3(7, BB), 256, CONV2_SMEM>>>();
    k_bnpool2<<<dim3(128, BB), 196>>>(bn2g, bn2b);

    // residual block
    k_resconv1<<<dim3(8, BB / 4), 196>>>(rc1w);
    k_shortcut<<<dim3(8, BB), 196>>>(rsw);
    k_chstats<<<256, 128>>>(rbn1g, rbn1b);
    k_resconv2<<<dim3(8, BB / 4), 196>>>(rc2w);
    k_chstats2<<<256, 128>>>(rbn2g, rbn2b, rbnsg, rbnsb);

    k_tail<<<64, 256>>>(out);
}

// round 14
// speedup vs baseline: 1.0621x; 1.0621x over previous
#include <cuda_runtime.h>
#include <math.h>

#define BB 64

// ---------------------------------------------------------------------------
// Scratch
// ---------------------------------------------------------------------------
__device__ float g_pooled1[BB * 3];
__device__ float g_attn1[BB * 8];
__device__ float g_w1t[BB * 64 * 168];           // tf32-rounded, padded [co][ci][kh][8]
__device__ float g_conv1[BB * 64 * 112 * 112];
__device__ float g_pool1[BB * 64 * 56 * 56];     // tf32-rounded (conv2 input)
__device__ float g_pooled2[BB * 64];
__device__ float g_attn2[BB * 8];
__device__ float g_w2[BB * 128 * 64 * 9];        // tf32-rounded
__device__ float g_conv2[BB * 128 * 28 * 28];
__device__ float g_pool2[BB * 128 * 14 * 14];
__device__ float g_rc1[BB * 256 * 49];
__device__ float g_rc2[BB * 256 * 49];
__device__ float g_rs[BB * 256 * 49];

__device__ float g_sum1[64],  g_sq1[64],  g_sc1[64],  g_sh1[64];
__device__ float g_sum2[128], g_sq2[128], g_sc2[128], g_sh2[128];
__device__ float g_scr1[256], g_shr1[256];
__device__ float g_scr2[256], g_shr2[256];
__device__ float g_scs[256],  g_shs[256];

__device__ float g_T[50 * 1024];
__device__ float g_M[50 * 256];
__device__ float g_b2[50];

// ---------------------------------------------------------------------------
// bn scale/shift (stages 0,1)
// ---------------------------------------------------------------------------
__global__ void k_bnscale(const float* __restrict__ g, const float* __restrict__ be,
                          float cnt, int stage, int C) {
    int c = blockIdx.x * blockDim.x + threadIdx.x;
    if (c >= C) return;
    float *su, *sq, *sc, *sh;
    if (stage == 0) { su = g_sum1; sq = g_sq1; sc = g_sc1; sh = g_sh1; }
    else            { su = g_sum2; sq = g_sq2; sc = g_sc2; sh = g_sh2; }
    float m = su[c] / cnt;
    float v = sq[c] / cnt - m * m;
    float s = g[c] * rsqrtf(v + 1e-5f);
    sc[c] = s;
    sh[c] = be[c] - m * s;
}

// per-channel stats of rc1 + finalize scale/shift
__global__ void k_chstats(const float* __restrict__ g, const float* __restrict__ be) {
    int c = blockIdx.x;
    float s = 0.f, q = 0.f;
    for (int t = threadIdx.x; t < BB * 49; t += 128) {
        int b = t / 49, p = t - b * 49;
        float v = g_rc1[(b * 256 + c) * 49 + p];
        s += v; q += v * v;
    }
    for (int o = 16; o; o >>= 1) {
        s += __shfl_down_sync(0xffffffffu, s, o);
        q += __shfl_down_sync(0xffffffffu, q, o);
    }
    __shared__ float rs[4], rq[4];
    int w = threadIdx.x >> 5;
    if ((threadIdx.x & 31) == 0) { rs[w] = s; rq[w] = q; }
    __syncthreads();
    if (threadIdx.x == 0) {
        float su = rs[0] + rs[1] + rs[2] + rs[3];
        float sq = rq[0] + rq[1] + rq[2] + rq[3];
        float m = su * (1.f / 3136.f);
        float v = sq * (1.f / 3136.f) - m * m;
        float sc = g[c] * rsqrtf(v + 1e-5f);
        g_scr1[c] = sc;
        g_shr1[c] = be[c] - m * sc;
    }
}

// stats of rc2 AND rs + finalize both scale/shifts
__global__ void k_chstats2(const float* __restrict__ g2, const float* __restrict__ be2,
                           const float* __restrict__ gs, const float* __restrict__ bes) {
    int c = blockIdx.x;
    float s2 = 0.f, q2 = 0.f, ss = 0.f, qs = 0.f;
    for (int t = threadIdx.x; t < BB * 49; t += 128) {
        int b = t / 49, p = t - b * 49;
        float v = g_rc2[(b * 256 + c) * 49 + p];
        s2 += v; q2 += v * v;
        float u = g_rs[(b * 256 + c) * 49 + p];
        ss += u; qs += u * u;
    }
    for (int o = 16; o; o >>= 1) {
        s2 += __shfl_down_sync(0xffffffffu, s2, o);
        q2 += __shfl_down_sync(0xffffffffu, q2, o);
        ss += __shfl_down_sync(0xffffffffu, ss, o);
        qs += __shfl_down_sync(0xffffffffu, qs, o);
    }
    __shared__ float r[4][4];
    int w = threadIdx.x >> 5;
    if ((threadIdx.x & 31) == 0) { r[w][0] = s2; r[w][1] = q2; r[w][2] = ss; r[w][3] = qs; }
    __syncthreads();
    if (threadIdx.x == 0) {
        float su2 = r[0][0] + r[1][0] + r[2][0] + r[3][0];
        float sq2 = r[0][1] + r[1][1] + r[2][1] + r[3][1];
        float sus = r[0][2] + r[1][2] + r[2][2] + r[3][2];
        float sqs = r[0][3] + r[1][3] + r[2][3] + r[3][3];
        float m2 = su2 * (1.f / 3136.f);
        float v2 = sq2 * (1.f / 3136.f) - m2 * m2;
        float c2 = g2[c] * rsqrtf(v2 + 1e-5f);
        g_scr2[c] = c2;
        g_shr2[c] = be2[c] - m2 * c2;
        float ms = sus * (1.f / 3136.f);
        float vs = sqs * (1.f / 3136.f) - ms * ms;
        float cs = gs[c] * rsqrtf(vs + 1e-5f);
        g_scs[c] = cs;
        g_shs[c] = bes[c] - ms * cs;
    }
}

// ---------------------------------------------------------------------------
// Stage-1 attention
// ---------------------------------------------------------------------------
__global__ void k_pooled1(const float* __restrict__ imgs) {
    int bc = blockIdx.x;
    int tid = threadIdx.x;
    if (bc == 0) {
        for (int i = tid; i < BB * 64; i += 256) g_pooled2[i] = 0.f;
        if (tid < 64)  { g_sum1[tid] = 0.f; g_sq1[tid] = 0.f; }
        if (tid < 128) { g_sum2[tid] = 0.f; g_sq2[tid] = 0.f; }
    }
    const float* p = imgs + (long)bc * 50176;
    float s = 0.f;
    for (int i = tid; i < 50176; i += 256) s += p[i];
    __shared__ float red[256];
    red[tid] = s; __syncthreads();
    for (int o = 128; o; o >>= 1) { if (tid < o) red[tid] += red[tid + o]; __syncthreads(); }
    if (tid == 0) g_pooled1[bc] = red[0] * (1.f / 50176.f);
}

__global__ void k_attn1(const float* __restrict__ fc1, const float* __restrict__ fc2,
                        const float* __restrict__ fc2b) {
    int b = threadIdx.x;
    if (b >= BB) return;
    float p[3];
    for (int c = 0; c < 3; c++) p[c] = g_pooled1[b * 3 + c];
    float h[8];
    for (int j = 0; j < 8; j++) {
        float s = 0.f;
        for (int c = 0; c < 3; c++) s += p[c] * fc1[j * 3 + c];
        h[j] = fmaxf(s, 0.f);
    }
    float lg[8], mx = -1e30f;
    for (int k = 0; k < 8; k++) {
        float s = fc2b[k];
        for (int j = 0; j < 8; j++) s += h[j] * fc2[k * 8 + j];
        lg[k] = s; mx = fmaxf(mx, s);
    }
    float den = 0.f;
    for (int k = 0; k < 8; k++) { lg[k] = expf(lg[k] - mx); den += lg[k]; }
    float inv = 1.f / den;
    for (int k = 0; k < 8; k++) g_attn1[b * 8 + k] = lg[k] * inv;
}

// aggregate + tf32-round + pad into [b][co][ci][kh][8] (kw slot 7 = 0)
__global__ void k_w1agg(const float* __restrict__ dy1) {
    int idx = blockIdx.x * 256 + threadIdx.x;
    if (idx >= BB * 10752) return;
    int b = idx / 10752, r = idx - b * 10752;
    int co = r / 168, r2 = r - co * 168;
    int ci = r2 / 56, r3 = r2 - ci * 56;
    int kh = r3 >> 3, kw = r3 & 7;
    float s = 0.f;
    if (kw < 7) {
        int i = co * 147 + ci * 49 + kh * 7 + kw;
#pragma unroll
        for (int k = 0; k < 8; k++) s += g_attn1[b * 8 + k] * dy1[k * 9408 + i];
    }
    unsigned tv; asm("cvt.rna.tf32.f32 %0, %1;" : "=r"(tv) : "f"(s));
    g_w1t[idx] = __uint_as_float(tv);
}

// ---------------------------------------------------------------------------
// Conv1 via tf32 mma.sync implicit GEMM (R11 champion form).
// grid (49, 64 b), 256 threads (8 warps, 2 mtiles x 8 ntiles each).
// ---------------------------------------------------------------------------
#define W_STRIDE 172
extern __shared__ float smemBuf[];
__global__ void __launch_bounds__(256, 2) k_conv1(const float* __restrict__ imgs) {
    float* s_in = smemBuf;                   // [ci][37][64]
    float* s_w = smemBuf + 7104;             // [co][W_STRIDE]
    float* s_stat = smemBuf + 7104 + 64 * W_STRIDE;
    int b = blockIdx.y;
    int tr = blockIdx.x / 7, tc = blockIdx.x - tr * 7;
    int oh0 = tr * 16, ow0 = tc * 16;
    int tid = threadIdx.x;

    if (tid < 128) s_stat[tid] = 0.f;

    const float* wt = g_w1t + b * 10752;
    for (int t = tid; t < 10752; t += 256)
        s_w[t + (t / 168) * 4] = wt[t];

    int ih0 = 2 * oh0 - 3, iw0 = 2 * ow0 - 3;
#pragma unroll 1
    for (int ci = 0; ci < 3; ci++) {
        const float* ip = imgs + (long)(b * 3 + ci) * 50176;
        for (int u = tid; u < 2368; u += 256) {
            int r = u >> 6, c = u & 63;
            if (c < 38) {
                int ih = ih0 + r, iw = iw0 + c;
                float v = 0.f;
                if ((unsigned)ih < 224u && (unsigned)iw < 224u)
                    v = ip[ih * 224 + iw];
                unsigned tv; asm("cvt.rna.tf32.f32 %0, %1;" : "=r"(tv) : "f"(v));
                s_in[ci * 2368 + u] = __uint_as_float(tv);
            }
        }
    }
    __syncthreads();

    int w = tid >> 5, lane = tid & 31;
    int gid = lane >> 2, tig = lane & 3;

    float acc[2][8][4];
#pragma unroll
    for (int mt = 0; mt < 2; mt++)
#pragma unroll
        for (int nt = 0; nt < 8; nt++)
#pragma unroll
            for (int k = 0; k < 4; k++) acc[mt][nt][k] = 0.f;

    int bq[8];
#pragma unroll
    for (int nt = 0; nt < 8; nt++) bq[nt] = (nt * 8 + gid) * W_STRIDE + tig;
    int abase0 = (2 * (2 * w + 0)) * 64 + 2 * gid + tig;
    int abase1 = (2 * (2 * w + 1)) * 64 + 2 * gid + tig;

#pragma unroll 1
    for (int ci = 0; ci < 3; ci++) {
#pragma unroll
        for (int kh = 0; kh < 7; kh++) {
            int wbase = ci * 56 + kh * 8;
            int aoff = ci * 2368 + kh * 64;
            unsigned bf0[8], bf1[8];
#pragma unroll
            for (int nt = 0; nt < 8; nt++) {
                bf0[nt] = __float_as_uint(s_w[bq[nt] + wbase]);
                bf1[nt] = __float_as_uint(s_w[bq[nt] + wbase + 4]);
            }
#pragma unroll
            for (int mt = 0; mt < 2; mt++) {
                int a = aoff + (mt ? abase1 : abase0);
                unsigned a0 = __float_as_uint(s_in[a]);
                unsigned a1 = __float_as_uint(s_in[a + 16]);
                unsigned a2 = __float_as_uint(s_in[a + 4]);
                unsigned a3 = __float_as_uint(s_in[a + 20]);
#pragma unroll
                for (int nt = 0; nt < 8; nt++) {
                    asm volatile(
                        "mma.sync.aligned.m16n8k8.row.col.f32.tf32.tf32.f32 "
                        "{%0,%1,%2,%3}, {%4,%5,%6,%7}, {%8,%9}, {%0,%1,%2,%3};"
                        : "+f"(acc[mt][nt][0]), "+f"(acc[mt][nt][1]),
                          "+f"(acc[mt][nt][2]), "+f"(acc[mt][nt][3])
                        : "r"(a0), "r"(a1), "r"(a2), "r"(a3),
                          "r"(bf0[nt]), "r"(bf1[nt]));
                }
            }
        }
    }

#pragma unroll
    for (int mt = 0; mt < 2; mt++) {
        int oh = oh0 + 2 * w + mt;
#pragma unroll
        for (int nt = 0; nt < 8; nt++) {
            int co = nt * 8 + 2 * tig;
            long base0 = ((long)(b * 64 + co)) * 12544 + oh * 112 + ow0;
            g_conv1[base0 + gid] = acc[mt][nt][0];
            g_conv1[base0 + 12544 + gid] = acc[mt][nt][1];
            g_conv1[base0 + gid + 8] = acc[mt][nt][2];
            g_conv1[base0 + 12544 + gid + 8] = acc[mt][nt][3];
        }
    }

#pragma unroll
    for (int nt = 0; nt < 8; nt++) {
        float s0 = 0.f, q0 = 0.f, s1 = 0.f, q1 = 0.f;
#pragma unroll
        for (int mt = 0; mt < 2; mt++) {
            float v;
            v = acc[mt][nt][0]; s0 += v; q0 += v * v;
            v = acc[mt][nt][2]; s0 += v; q0 += v * v;
            v = acc[mt][nt][1]; s1 += v; q1 += v * v;
            v = acc[mt][nt][3]; s1 += v; q1 += v * v;
        }
#pragma unroll
        for (int o = 16; o >= 4; o >>= 1) {
            s0 += __shfl_xor_sync(0xffffffffu, s0, o);
            q0 += __shfl_xor_sync(0xffffffffu, q0, o);
            s1 += __shfl_xor_sync(0xffffffffu, s1, o);
            q1 += __shfl_xor_sync(0xffffffffu, q1, o);
        }
        if (gid == 0) {
            int co = nt * 8 + 2 * tig;
            atomicAdd(&s_stat[co], s0);
            atomicAdd(&s_stat[64 + co], q0);
            atomicAdd(&s_stat[co + 1], s1);
            atomicAdd(&s_stat[64 + co + 1], q1);
        }
    }
    __syncthreads();
    if (tid < 64) {
        atomicAdd(&g_sum1[tid], s_stat[tid]);
        atomicAdd(&g_sq1[tid], s_stat[64 + tid]);
    }
}
#define CONV1_SMEM ((7104 + 64 * W_STRIDE + 128) * 4)

// ---------------------------------------------------------------------------
// BN1 + maxpool3 s2 p1: 112->56, plane-tiled; output tf32-rounded
// ---------------------------------------------------------------------------
extern __shared__ float s_plane[];
__global__ void __launch_bounds__(256) k_bnpool1() {
    int c = blockIdx.x, b = blockIdx.y;
    int tid = threadIdx.x;
    const float* ip = g_conv1 + (long)(b * 64 + c) * 12544;
#pragma unroll
    for (int k = 0; k < 49; k++) s_plane[tid + 256 * k] = ip[tid + 256 * k];
    __syncthreads();

    float sc = g_sc1[c], sh = g_sh1[c];
    float* op = g_pool1 + (b * 64 + c) * 3136;
    float s = 0.f;
#pragma unroll
    for (int k = 0; k < 13; k++) {
        int p = tid + 256 * k;
        if (p < 3136) {
            int oh = p / 56, ow = p - oh * 56;
            float m = -1e30f;
#pragma unroll
            for (int r = 0; r < 3; r++) {
                int ih = 2 * oh - 1 + r;
                if ((unsigned)ih >= 112u) continue;
#pragma unroll
                for (int cc = 0; cc < 3; cc++) {
                    int iw = 2 * ow - 1 + cc;
                    if ((unsigned)iw >= 112u) continue;
                    m = fmaxf(m, s_plane[ih * 112 + iw] * sc + sh);
                }
            }
            unsigned tv; asm("cvt.rna.tf32.f32 %0, %1;" : "=r"(tv) : "f"(m));
            op[p] = __uint_as_float(tv);
            s += m;
        }
    }
    for (int o = 16; o; o >>= 1) s += __shfl_down_sync(0xffffffffu, s, o);
    __shared__ float s_red;
    if (tid == 0) s_red = 0.f;
    __syncthreads();
    if ((tid & 31) == 0) atomicAdd(&s_red, s);
    __syncthreads();
    if (tid == 0) atomicAdd(&g_pooled2[b * 64 + c], s_red);
}
#define POOL1_SMEM (12544 * 4)

// ---------------------------------------------------------------------------
// Stage-2 attention
// ---------------------------------------------------------------------------
__global__ void k_attn2(const float* __restrict__ fc1, const float* __restrict__ fc2,
                        const float* __restrict__ fc2b) {
    int b = threadIdx.x;
    if (b >= BB) return;
    float h[17];
    for (int j = 0; j < 17; j++) {
        float s = 0.f;
        for (int c = 0; c < 64; c++)
            s += (g_pooled2[b * 64 + c] * (1.f / 3136.f)) * fc1[j * 64 + c];
        h[j] = fmaxf(s, 0.f);
    }
    float lg[8], mx = -1e30f;
    for (int k = 0; k < 8; k++) {
        float s = fc2b[k];
        for (int j = 0; j < 17; j++) s += h[j] * fc2[k * 17 + j];
        lg[k] = s; mx = fmaxf(mx, s);
    }
    float den = 0.f;
    for (int k = 0; k < 8; k++) { lg[k] = expf(lg[k] - mx); den += lg[k]; }
    float inv = 1.f / den;
    for (int k = 0; k < 8; k++) g_attn2[b * 8 + k] = lg[k] * inv;
}

// aggregate + tf32-round
__global__ void k_w2agg(const float* __restrict__ dy2) {
    int idx = blockIdx.x * 256 + threadIdx.x;
    if (idx >= BB * 73728) return;
    int b = idx / 73728, i = idx - b * 73728;
    float s = 0.f;
#pragma unroll
    for (int k = 0; k < 8; k++) s += g_attn2[b * 8 + k] * dy2[k * 73728 + i];
    unsigned tv; asm("cvt.rna.tf32.f32 %0, %1;" : "=r"(tv) : "f"(s));
    g_w2[idx] = __uint_as_float(tv);
}

// ---------------------------------------------------------------------------
// Conv2 via tf32 mma.sync (R11 champion form: 128 co/block).
// grid (7 rowblk, 64 b), 256 threads, warps 0-6 mma.
// ---------------------------------------------------------------------------
__global__ void __launch_bounds__(256, 2) k_conv2() {
    float* s_in = smemBuf;                 // 4698
    float* s_w = smemBuf + 4698;           // 10368
    float* s_stat = smemBuf + 4698 + 10368;
    int rowblk = blockIdx.x, b = blockIdx.y;
    int tid = threadIdx.x;

    for (int t = tid; t < 4698; t += 256) s_in[t] = 0.f;
    s_stat[tid] = 0.f;

    int ih0 = 8 * rowblk - 1;
    int ldp[8], stp[8];
#pragma unroll
    for (int k = 0; k < 8; k++) {
        int e2 = tid + 256 * k;
        if (e2 < 2016) {
            int ci = e2 / 252, rem = e2 - ci * 252;
            int ir = rem / 28, iw2 = rem - ir * 28;
            int ih = ih0 + ir;
            ldp[k] = (ih >= 0) ? (ci * 3136 + ih * 56 + 2 * iw2) : -1;
            stp[k] = ir * 522 + (2 * iw2 + 1) * 9 + ci;
        } else { ldp[k] = -1; stp[k] = 0; }
    }

    int w = tid >> 5, lane = tid & 31;
    int gid = lane >> 2, tig = lane & 3;
    int q0 = 16 * w + gid, q1 = q0 + 8;
    int ohl0 = q0 / 28, owl0 = q0 - 28 * ohl0;
    int ohl1 = q1 / 28, owl1 = q1 - 28 * ohl1;
    int pb0 = 2 * ohl0 * 522 + 2 * owl0 * 9 + tig;
    int pb1 = 2 * ohl1 * 522 + 2 * owl1 * 9 + tig;

    float acc[16][4];
#pragma unroll
    for (int nt = 0; nt < 16; nt++)
#pragma unroll
        for (int k = 0; k < 4; k++) acc[nt][k] = 0.f;

    const float* ib = g_pool1 + (long)(b * 64) * 3136;
    const float* wb = g_w2 + b * 73728;
    int half = tid & 1, co_t = tid >> 1;

#pragma unroll 1
    for (int c0 = 0; c0 < 64; c0 += 8) {
        __syncthreads();
#pragma unroll
        for (int k = 0; k < 8; k++) {
            if (ldp[k] >= 0) {
                float2 v = *(const float2*)(ib + c0 * 3136 + ldp[k]);
                s_in[stp[k]] = v.x;
                s_in[stp[k] + 9] = v.y;
            }
        }
        {
            const float4* src = (const float4*)(wb + co_t * 576 + c0 * 9 + half * 36);
            int sb = co_t * 9;
            int cb = half * 4;
#pragma unroll
            for (int q = 0; q < 9; q++) {
                float4 f = src[q];
                int e0 = 4 * q;
                s_w[((e0    ) % 9) * 1152 + sb + cb + (e0    ) / 9] = f.x;
                s_w[((e0 + 1) % 9) * 1152 + sb + cb + (e0 + 1) / 9] = f.y;
                s_w[((e0 + 2) % 9) * 1152 + sb + cb + (e0 + 2) / 9] = f.z;
                s_w[((e0 + 3) % 9) * 1152 + sb + cb + (e0 + 3) / 9] = f.w;
            }
        }
        __syncthreads();
        if (w < 7) {
#pragma unroll
            for (int tap = 0; tap < 9; tap++) {
                int kh = tap / 3, kw = tap - 3 * (tap / 3);
                int toff = kh * 522 + kw * 9;
                unsigned a0 = __float_as_uint(s_in[pb0 + toff]);
                unsigned a1 = __float_as_uint(s_in[pb1 + toff]);
                unsigned a2 = __float_as_uint(s_in[pb0 + toff + 4]);
                unsigned a3 = __float_as_uint(s_in[pb1 + toff + 4]);
#pragma unroll
                for (int nt = 0; nt < 16; nt++) {
                    int wq = tap * 1152 + (nt * 8 + gid) * 9 + tig;
                    unsigned b0 = __float_as_uint(s_w[wq]);
                    unsigned b1 = __float_as_uint(s_w[wq + 4]);
                    asm volatile(
                        "mma.sync.aligned.m16n8k8.row.col.f32.tf32.tf32.f32 "
                        "{%0,%1,%2,%3}, {%4,%5,%6,%7}, {%8,%9}, {%0,%1,%2,%3};"
                        : "+f"(acc[nt][0]), "+f"(acc[nt][1]),
                          "+f"(acc[nt][2]), "+f"(acc[nt][3])
                        : "r"(a0), "r"(a1), "r"(a2), "r"(a3),
                          "r"(b0), "r"(b1));
                }
            }
        }
    }

    if (w < 7) {
#pragma unroll
        for (int nt = 0; nt < 16; nt++) {
            int co = nt * 8 + 2 * tig;
            long o0 = ((long)(b * 128 + co)) * 784 + rowblk * 112;
            g_conv2[o0 + q0] = acc[nt][0];
            g_conv2[o0 + 784 + q0] = acc[nt][1];
            g_conv2[o0 + q1] = acc[nt][2];
            g_conv2[o0 + 784 + q1] = acc[nt][3];
            float s0 = acc[nt][0] + acc[nt][2];
            float sq0 = acc[nt][0] * acc[nt][0] + acc[nt][2] * acc[nt][2];
            float s1 = acc[nt][1] + acc[nt][3];
            float sq1 = acc[nt][1] * acc[nt][1] + acc[nt][3] * acc[nt][3];
#pragma unroll
            for (int o = 16; o >= 4; o >>= 1) {
                s0 += __shfl_xor_sync(0xffffffffu, s0, o);
                sq0 += __shfl_xor_sync(0xffffffffu, sq0, o);
                s1 += __shfl_xor_sync(0xffffffffu, s1, o);
                sq1 += __shfl_xor_sync(0xffffffffu, sq1, o);
            }
            if (gid == 0) {
                atomicAdd(&s_stat[co], s0);
                atomicAdd(&s_stat[128 + co], sq0);
                atomicAdd(&s_stat[co + 1], s1);
                atomicAdd(&s_stat[128 + co + 1], sq1);
            }
        }
    }
    __syncthreads();
    if (tid < 128) {
        atomicAdd(&g_sum2[tid], s_stat[tid]);
        atomicAdd(&g_sq2[tid], s_stat[128 + tid]);
    }
}
#define CONV2_SMEM ((4698 + 10368 + 256) * 4)

// ---------------------------------------------------------------------------
// BN2 + maxpool3 s2 p1: 28->14
// ---------------------------------------------------------------------------
__global__ void k_bnpool2() {
    int b = blockIdx.y, c = blockIdx.x;
    int p = threadIdx.x;
    if (p >= 196) return;
    int oh = p / 14, ow = p - oh * 14;
    float sc = g_sc2[c], sh = g_sh2[c];
    const float* ip = g_conv2 + (b * 128 + c) * 784;
    float m = -1e30f;
#pragma unroll
    for (int r = 0; r < 3; r++) {
        int ih = 2 * oh - 1 + r;
        if ((unsigned)ih >= 28u) continue;
#pragma unroll
        for (int cc = 0; cc < 3; cc++) {
            int iw = 2 * ow - 1 + cc;
            if ((unsigned)iw >= 28u) continue;
            m = fmaxf(m, ip[ih * 28 + iw] * sc + sh);
        }
    }
    g_pool2[(b * 128 + c) * 196 + p] = m;
}

// ---------------------------------------------------------------------------
// resconv1 + fused shortcut: 128->256 3x3 s2 AND 1x1 s2, 14->7.
// 4 batches/block, pipelined staging. Shortcut ci order ascending (bitwise
// identical to the standalone kernel). grid (8 cog, 16 bq), block 196.
// ---------------------------------------------------------------------------
__global__ void __launch_bounds__(196) k_resconv1(const float* __restrict__ w,
                                                  const float* __restrict__ ws) {
    __shared__ __align__(16) float s_in[4 * 1080];
    __shared__ __align__(16) float s_w[32 * 48];
    __shared__ __align__(16) float s_ws[32 * 128];
    int bq = blockIdx.y, cog = blockIdx.x;
    int b0 = bq * 4;
    int tid = threadIdx.x;
    int px = tid % 49, yq = tid / 49;
    int oh = px / 7, ow = px - oh * 7;

    for (int t = tid; t < 4320; t += 196) s_in[t] = 0.f;
    for (int t = tid; t < 1536; t += 196) s_w[t] = 0.f;
    for (int t = tid; t < 4096; t += 196)
        s_ws[t] = ws[cog * 4096 + t];        // [co][ci], co-major

    int ld[16], sidx[16];
#pragma unroll
    for (int k = 0; k < 16; k++) {
        int t = tid + 196 * k;
        int bl = t / 784, rem = t - bl * 784;
        int ci = rem / 196, p = rem - ci * 196;
        int r = p / 14, c = p - r * 14;
        ld[k] = bl * 25088 + rem;
        sidx[k] = bl * 1080 + ci * 270 + (r + 1) * 18 + (c + 1);
    }
    int wld[6], wst[6];
#pragma unroll
    for (int k = 0; k < 6; k++) {
        int t = tid + 196 * k;
        if (t < 1152) {
            int co = t / 36, rem = t - co * 36;
            int ci = rem / 9, k9 = rem - ci * 9;
            int kh = k9 / 3, kw = k9 - kh * 3;
            wld[k] = (cog * 32 + co) * 1152 + ci * 9 + k9;
            wst[k] = co * 48 + ci * 12 + kh * 4 + kw;
        } else { wld[k] = -1; wst[k] = 1536 - 1; }
    }
    __syncthreads();

    const float* base = g_pool2 + (long)(b0 * 128) * 196;
    float r_in[16], r_w[6];
#pragma unroll
    for (int k = 0; k < 16; k++) r_in[k] = base[ld[k]];
#pragma unroll
    for (int k = 0; k < 6; k++) r_w[k] = (wld[k] >= 0) ? w[wld[k]] : 0.f;

    float acc[4][8], accS[4][8];
#pragma unroll
    for (int bl = 0; bl < 4; bl++)
#pragma unroll
        for (int co = 0; co < 8; co++) { acc[bl][co] = 0.f; accS[bl][co] = 0.f; }

    int cenoff = (2 * oh + 1) * 18 + (2 * ow + 1);

#pragma unroll 1
    for (int c0 = 0; c0 < 128; c0 += 4) {
#pragma unroll
        for (int k = 0; k < 16; k++) s_in[sidx[k]] = r_in[k];
#pragma unroll
        for (int k = 0; k < 6; k++) if (wld[k] >= 0) s_w[wst[k]] = r_w[k];
        __syncthreads();
        if (c0 + 4 < 128) {
            const float* src = base + (c0 + 4) * 196;
#pragma unroll
            for (int k = 0; k < 16; k++) r_in[k] = src[ld[k]];
#pragma unroll
            for (int k = 0; k < 6; k++)
                if (wld[k] >= 0) r_w[k] = w[wld[k] + (c0 + 4) * 9];
        }
#pragma unroll
        for (int ci = 0; ci < 4; ci++) {
#pragma unroll
            for (int kh = 0; kh < 3; kh++) {
                float in[4][3];
#pragma unroll
                for (int bl = 0; bl < 4; bl++) {
                    int bs = bl * 1080 + ci * 270 + (2 * oh + kh) * 18 + 2 * ow;
                    in[bl][0] = s_in[bs];
                    in[bl][1] = s_in[bs + 1];
                    in[bl][2] = s_in[bs + 2];
                }
#pragma unroll
                for (int co = 0; co < 8; co++) {
                    const float4* wp = (const float4*)(s_w + (yq * 8 + co) * 48 + ci * 12 + kh * 4);
                    float4 wv = wp[0];
#pragma unroll
                    for (int bl = 0; bl < 4; bl++) {
                        acc[bl][co] += wv.x * in[bl][0];
                        acc[bl][co] += wv.y * in[bl][1];
                        acc[bl][co] += wv.z * in[bl][2];
                    }
                }
            }
            // fused shortcut: center sample, same ci ascending order
            float cen[4];
#pragma unroll
            for (int bl = 0; bl < 4; bl++)
                cen[bl] = s_in[bl * 1080 + ci * 270 + cenoff];
#pragma unroll
            for (int co = 0; co < 8; co++) {
                float wsv = s_ws[(yq * 8 + co) * 128 + c0 + ci];
#pragma unroll
                for (int bl = 0; bl < 4; bl++)
                    accS[bl][co] += wsv * cen[bl];
            }
        }
        __syncthreads();
    }
#pragma unroll
    for (int bl = 0; bl < 4; bl++)
#pragma unroll
        for (int co = 0; co < 8; co++) {
            int oidx = ((b0 + bl) * 256 + cog * 32 + yq * 8 + co) * 49 + px;
            g_rc1[oidx] = acc[bl][co];
            g_rs[oidx] = accS[bl][co];
        }
}

// ---------------------------------------------------------------------------
// resconv2: 256->256 3x3 s1, 7x7. bn+relu at register-load time, pipelined.
// ---------------------------------------------------------------------------
__global__ void __launch_bounds__(196) k_resconv2(const float* __restrict__ w) {
    __shared__ __align__(16) float s_in[4 * 432];
    __shared__ __align__(16) float s_w[32 * 48];
    int bq = blockIdx.y, cog = blockIdx.x;
    int b0 = bq * 4;
    int tid = threadIdx.x;
    int px = tid % 49, yq = tid / 49;
    int oh = px / 7, ow = px - oh * 7;

    for (int t = tid; t < 1728; t += 196) s_in[t] = 0.f;
    for (int t = tid; t < 1536; t += 196) s_w[t] = 0.f;

    int ld[4], sidx[4], cidx[4];
#pragma unroll
    for (int k = 0; k < 4; k++) {
        int t = tid + 196 * k;
        int bl = t / 196, rem = t - bl * 196;
        int ci = rem / 49, p = rem - ci * 49;
        int r = p / 7, c = p - r * 7;
        ld[k] = bl * 12544 + rem;
        sidx[k] = bl * 432 + ci * 108 + (r + 1) * 12 + (c + 1);
        cidx[k] = ci;
    }
    int wld[6], wst[6];
#pragma unroll
    for (int k = 0; k < 6; k++) {
        int t = tid + 196 * k;
        if (t < 1152) {
            int co = t / 36, rem = t - co * 36;
            int ci = rem / 9, k9 = rem - ci * 9;
            int kh = k9 / 3, kw = k9 - kh * 3;
            wld[k] = (cog * 32 + co) * 2304 + ci * 9 + k9;
            wst[k] = co * 48 + ci * 12 + kh * 4 + kw;
        } else { wld[k] = -1; wst[k] = 0; }
    }
    __syncthreads();

    const float* base = g_rc1 + (long)(b0 * 256) * 49;
    float r_in[4], r_w[6];
#pragma unroll
    for (int k = 0; k < 4; k++) {
        float sc = g_scr1[cidx[k]], sh = g_shr1[cidx[k]];
        r_in[k] = fmaxf(base[ld[k]] * sc + sh, 0.f);
    }
#pragma unroll
    for (int k = 0; k < 6; k++) r_w[k] = (wld[k] >= 0) ? w[wld[k]] : 0.f;

    float acc[4][8];
#pragma unroll
    for (int bl = 0; bl < 4; bl++)
#pragma unroll
        for (int co = 0; co < 8; co++) acc[bl][co] = 0.f;

#pragma unroll 1
    for (int c0 = 0; c0 < 256; c0 += 4) {
#pragma unroll
        for (int k = 0; k < 4; k++) s_in[sidx[k]] = r_in[k];
#pragma unroll
        for (int k = 0; k < 6; k++) if (wld[k] >= 0) s_w[wst[k]] = r_w[k];
        __syncthreads();
        if (c0 + 4 < 256) {
            const float* src = base + (c0 + 4) * 49;
#pragma unroll
            for (int k = 0; k < 4; k++) {
                int ch = c0 + 4 + cidx[k];
                float sc = g_scr1[ch], sh = g_shr1[ch];
                r_in[k] = fmaxf(src[ld[k]] * sc + sh, 0.f);
            }
#pragma unroll
            for (int k = 0; k < 6; k++)
                if (wld[k] >= 0) r_w[k] = w[wld[k] + (c0 + 4) * 9];
        }
#pragma unroll
        for (int ci = 0; ci < 4; ci++) {
#pragma unroll
            for (int kh = 0; kh < 3; kh++) {
                float in[4][3];
#pragma unroll
                for (int bl = 0; bl < 4; bl++) {
                    int bs = bl * 432 + ci * 108 + (oh + kh) * 12 + ow;
                    in[bl][0] = s_in[bs];
                    in[bl][1] = s_in[bs + 1];
                    in[bl][2] = s_in[bs + 2];
                }
#pragma unroll
                for (int co = 0; co < 8; co++) {
                    const float4* wp = (const float4*)(s_w + (yq * 8 + co) * 48 + ci * 12 + kh * 4);
                    float4 wv = wp[0];
#pragma unroll
                    for (int bl = 0; bl < 4; bl++) {
                        acc[bl][co] += wv.x * in[bl][0];
                        acc[bl][co] += wv.y * in[bl][1];
                        acc[bl][co] += wv.z * in[bl][2];
                    }
                }
            }
        }
        __syncthreads();
    }
#pragma unroll
    for (int bl = 0; bl < 4; bl++)
#pragma unroll
        for (int co = 0; co < 8; co++)
            g_rc2[((b0 + bl) * 256 + cog * 32 + yq * 8 + co) * 49 + px] = acc[bl][co];
}

// ---------------------------------------------------------------------------
// tail: y = mean relu(bn(rc2)+bn(rs)); out = y M^T + b2
// ---------------------------------------------------------------------------
__global__ void k_tail(float* __restrict__ out) {
    __shared__ float s_y[256];
    int b = blockIdx.x, c = threadIdx.x;
    float sc2 = g_scr2[c], sh2 = g_shr2[c], scs = g_scs[c], shs = g_shs[c];
    const float* p2 = g_rc2 + (b * 256 + c) * 49;
    const float* ps = g_rs + (b * 256 + c) * 49;
    float s = 0.f;
    for (int p = 0; p < 49; p++) {
        float v = p2[p] * sc2 + sh2 + ps[p] * scs + shs;
        s += fmaxf(v, 0.f);
    }
    s_y[c] = s * (1.f / 49.f);
    __syncthreads();
    if (c < 50) {
        float acc = g_b2[c];
        for (int k = 0; k < 256; k++) acc += s_y[k] * g_M[c * 256 + k];
        out[b * 50 + c] = acc;
    }
}

// ---------------------------------------------------------------------------
// Tail fold (softmax attention collapses to 1x1 conv: wo@wv)
// ---------------------------------------------------------------------------
__global__ void k_foldT(const float* __restrict__ fcw, const float* __restrict__ wo) {
    int idx = blockIdx.x * 256 + threadIdx.x;
    if (idx >= 50 * 1024) return;
    int i = idx / 1024, j = idx - i * 1024;
    float s = 0.f;
    for (int c = 0; c < 256; c++) s += fcw[i * 256 + c] * wo[c * 1024 + j];
    g_T[idx] = s;
}

__global__ void k_foldM(const float* __restrict__ wv) {
    int idx = blockIdx.x * 256 + threadIdx.x;
    if (idx >= 50 * 256) return;
    int i = idx / 256, c = idx - i * 256;
    float s = 0.f;
    for (int j = 0; j < 1024; j++) s += g_T[i * 1024 + j] * wv[j * 256 + c];
    g_M[idx] = s;
}

__global__ void k_foldb(const float* __restrict__ fcw, const float* __restrict__ bo,
                        const float* __restrict__ fcb) {
    int i = threadIdx.x;
    if (i >= 50) return;
    float s = 0.f;
    for (int c = 0; c < 256; c++) s += fcw[i * 256 + c] * bo[c];
    g_b2[i] = s + fcb[i];
}

// ---------------------------------------------------------------------------
// Launch (k_conv1 is the 4th launch -> ncu profile target / control)
// ---------------------------------------------------------------------------
extern "C" void kernel_launch(void* const* d_in, const int* in_sizes, int n_in,
                              void* d_out, int out_size) {
    const float* imgs   = (const float*)d_in[0];
    const float* a1f1   = (const float*)d_in[1];
    const float* a1f2   = (const float*)d_in[2];
    const float* a1f2b  = (const float*)d_in[3];
    const float* dy1    = (const float*)d_in[4];
    const float* bn1g   = (const float*)d_in[5];
    const float* bn1b   = (const float*)d_in[6];
    const float* a2f1   = (const float*)d_in[7];
    const float* a2f2   = (const float*)d_in[8];
    const float* a2f2b  = (const float*)d_in[9];
    const float* dy2    = (const float*)d_in[10];
    const float* bn2g   = (const float*)d_in[11];
    const float* bn2b   = (const float*)d_in[12];
    const float* rc1w   = (const float*)d_in[13];
    const float* rbn1g  = (const float*)d_in[14];
    const float* rbn1b  = (const float*)d_in[15];
    const float* rc2w   = (const float*)d_in[16];
    const float* rbn2g  = (const float*)d_in[17];
    const float* rbn2b  = (const float*)d_in[18];
    const float* rsw    = (const float*)d_in[19];
    const float* rbnsg  = (const float*)d_in[20];
    const float* rbnsb  = (const float*)d_in[21];
    const float* wv     = (const float*)d_in[24];
    const float* wo     = (const float*)d_in[25];
    const float* bo     = (const float*)d_in[26];
    const float* fcw    = (const float*)d_in[27];
    const float* fcb    = (const float*)d_in[28];
    float* out = (float*)d_out;
    (void)in_sizes; (void)n_in; (void)out_size;

    static int smem_set = 0;
    if (!smem_set) {
        cudaFuncSetAttribute(k_conv1, cudaFuncAttributeMaxDynamicSharedMemorySize,
                             CONV1_SMEM);
        cudaFuncSetAttribute(k_conv1, cudaFuncAttributePreferredSharedMemoryCarveout,
                             100);
        cudaFuncSetAttribute(k_conv2, cudaFuncAttributeMaxDynamicSharedMemorySize,
                             CONV2_SMEM);
        cudaFuncSetAttribute(k_conv2, cudaFuncAttributePreferredSharedMemoryCarveout,
                             100);
        cudaFuncSetAttribute(k_bnpool1, cudaFuncAttributeMaxDynamicSharedMemorySize,
                             POOL1_SMEM);
        smem_set = 1;
    }

    // stage 1 front (block 0 of pooled1 zeroes accumulators)
    k_pooled1<<<192, 256>>>(imgs);
    k_attn1<<<1, 64>>>(a1f1, a1f2, a1f2b);
    k_w1agg<<<(BB * 10752 + 255) / 256, 256>>>(dy1);
    k_conv1<<<dim3(49, BB), 256, CONV1_SMEM>>>(imgs);  // 4th (profiled, control)

    // tail fold (independent)
    k_foldT<<<200, 256>>>(fcw, wo);
    k_foldM<<<50, 256>>>(wv);
    k_foldb<<<1, 64>>>(fcw, bo, fcb);

    k_bnscale<<<1, 64>>>(bn1g, bn1b, 802816.f, 0, 64);
    k_bnpool1<<<dim3(64, BB), 256, POOL1_SMEM>>>();

    // stage 2
    k_attn2<<<1, 64>>>(a2f1, a2f2, a2f2b);
    k_w2agg<<<(BB * 73728 + 255) / 256, 256>>>(dy2);
    k_conv2<<<dim3(7, BB), 256, CONV2_SMEM>>>();
    k_bnscale<<<1, 128>>>(bn2g, bn2b, 50176.f, 1, 128);
    k_bnpool2<<<dim3(128, BB), 196>>>();

    // residual block (shortcut fused into resconv1)
    k_resconv1<<<dim3(8, BB / 4), 196>>>(rc1w, rsw);
    k_chstats<<<256, 128>>>(rbn1g, rbn1b);
    k_resconv2<<<dim3(8, BB / 4), 196>>>(rc2w);
    k_chstats2<<<256, 128>>>(rbn2g, rbn2b, rbnsg, rbnsb);

    k_tail<<<64, 256>>>(out);
}